// round 1
// baseline (speedup 1.0000x reference)
#include <cuda_runtime.h>
#include <cuda_fp16.h>

namespace {

constexpr int BB = 256;   // batch
constexpr int TT = 512;   // time steps
constexpr int DD = 64;    // feature dim
constexpr int HH = 128;   // hidden dim
constexpr int NB = 2;     // batches per block
constexpr int NT = 256;   // threads per block
constexpr int KC = DD + HH + DD;   // 256 (combined width)
constexpr int KC2 = KC / 2;        // 128 (k-pairs)

// Shared memory layout.
// Weights stored fp16, k-pair-major: wX[k2][j] = half2{ W[j][2k2], W[j][2k2+1] }.
// Warp lanes = consecutive j -> conflict-free LDS; combined/c vectors are
// warp-uniform broadcast loads.
struct __align__(16) Smem {
    __half2 wz[KC2][HH];      // 65536 B
    __half2 wr[KC2][HH];      // 65536 B
    __half2 wh[KC2][HH];      // 65536 B
    __half2 wgh[DD / 2][HH];  // 16384 B
    float cr[NB][KC];         // combined_r = [x, r*h_pre, m]
    float c[NB][KC];          // combined   = [x,   h_pre, m]
    float in_s[4][NB][DD];    // this step's inputs: ch 0=x,1=x_last,2=m,3=d
    float h[NB][HH];          // recurrent state
    float zr[2][NB][HH];      // z (0) and r (1) gates
    float part[2][NB][HH];    // h_tilde K-split partial sums
    float bgx[DD], wgxd[DD];
    float bgh[HH], bz[HH], br[HH], bh[HH];
};
// total ~226.8 KB < 227 KB opt-in limit

__global__ void __launch_bounds__(NT, 1) grud_kernel(
    const float* __restrict__ inp,   // [B,4,T,D]
    const float* __restrict__ Wgx, const float* __restrict__ bgx,
    const float* __restrict__ Wgh, const float* __restrict__ bgh,
    const float* __restrict__ Wz,  const float* __restrict__ bz,
    const float* __restrict__ Wr,  const float* __restrict__ br,
    const float* __restrict__ Wh,  const float* __restrict__ bh,
    float* __restrict__ out)         // [B,T,H]
{
    extern __shared__ char smem_raw[];
    Smem& s = *reinterpret_cast<Smem*>(smem_raw);
    const int tid = threadIdx.x;
    const int b0  = blockIdx.x * NB;

    // ------- preamble: weights -> smem fp16, transposed to k-pair-major -----
    // Global reads are coalesced over k2 (float2, consecutive lanes 8B apart).
    for (int lin = tid; lin < HH * KC2; lin += NT) {
        int j = lin >> 7, k2 = lin & (KC2 - 1);
        float2 a = *(const float2*)&Wz[j * KC + 2 * k2];
        s.wz[k2][j] = __floats2half2_rn(a.x, a.y);
        float2 b = *(const float2*)&Wr[j * KC + 2 * k2];
        s.wr[k2][j] = __floats2half2_rn(b.x, b.y);
        float2 g = *(const float2*)&Wh[j * KC + 2 * k2];
        s.wh[k2][j] = __floats2half2_rn(g.x, g.y);
    }
    for (int lin = tid; lin < HH * (DD / 2); lin += NT) {
        int j = lin >> 5, k2 = lin & (DD / 2 - 1);
        float2 a = *(const float2*)&Wgh[j * DD + 2 * k2];
        s.wgh[k2][j] = __floats2half2_rn(a.x, a.y);
    }
    if (tid < HH) {
        s.bgh[tid] = bgh[tid]; s.bz[tid] = bz[tid];
        s.br[tid]  = br[tid];  s.bh[tid] = bh[tid];
        s.h[0][tid] = 0.f;     s.h[1][tid] = 0.f;
    }
    if (tid < DD) {
        s.bgx[tid]  = bgx[tid];
        s.wgxd[tid] = Wgx[tid * DD + tid];   // (eye * W_gx) -> diagonal
    }

    // ------- input prefetch: each thread owns one (ch, d) for both batches --
    const int ch = (tid >> 6) & 3;
    const int dl = tid & 63;
    const long base0 = ((long)(b0 * 4 + ch) * TT) * DD + dl;
    const long base1 = base0 + 4L * TT * DD;
    float nx0 = inp[base0];   // t = 0
    float nx1 = inp[base1];

    const int bq = tid >> 7;   // batch selector / gate selector / K-half
    const int j  = tid & 127;  // output row

    for (int t = 0; t < TT; ++t) {
        // stage 0: publish this step's inputs, prefetch next step's
        s.in_s[ch][0][dl] = nx0;
        s.in_s[ch][1][dl] = nx1;
        const int tn = (t + 1 < TT) ? (t + 1) : t;
        nx0 = inp[base0 + (long)tn * DD];
        nx1 = inp[base1 + (long)tn * DD];
        __syncthreads();

        // stage 1: delta_h and h_pre = delta_h * h  (all 256 threads);
        //          x update + m slot (threads 0..127)
        {
            float a0 = 0.f, a1 = 0.f;
            #pragma unroll
            for (int k2 = 0; k2 < DD / 2; k2 += 2) {
                float2 w0 = __half22float2(s.wgh[k2][j]);
                float2 w1 = __half22float2(s.wgh[k2 + 1][j]);
                float4 dv = *(const float4*)&s.in_s[3][bq][2 * k2];
                a0 = fmaf(w0.x, dv.x, fmaf(w0.y, dv.y, a0));
                a1 = fmaf(w1.x, dv.z, fmaf(w1.y, dv.w, a1));
            }
            float pre = a0 + a1 + s.bgh[j];
            float dh  = __expf(-fmaxf(pre, 0.f));
            s.c[bq][DD + j] = dh * s.h[bq][j];
        }
        if (tid < 128) {
            int b2 = tid >> 6, d = tid & 63;
            float dd = s.in_s[3][b2][d];
            float dx = __expf(-fmaxf(fmaf(dd, s.wgxd[d], s.bgx[d]), 0.f));
            float m  = s.in_s[2][b2][d];
            float xv = m * s.in_s[0][b2][d] + (1.f - m) * (dx * s.in_s[1][b2][d]);
            s.c[b2][d] = xv;
            s.c[b2][DD + HH + d] = m;
        }
        __syncthreads();

        // stage 2: z (warps 0-3) / r (warps 4-7); both batches per thread,
        // weight loaded once and reused across batches; 4 accumulator chains.
        {
            const __half2* wgt = bq ? &s.wr[0][0] : &s.wz[0][0];
            float a00 = 0.f, a01 = 0.f, a10 = 0.f, a11 = 0.f;
            #pragma unroll 8
            for (int k2 = 0; k2 < KC2; k2 += 2) {
                float2 w0 = __half22float2(wgt[k2 * HH + j]);
                float2 w1 = __half22float2(wgt[(k2 + 1) * HH + j]);
                float4 c0 = *(const float4*)&s.c[0][2 * k2];
                float4 c1 = *(const float4*)&s.c[1][2 * k2];
                a00 = fmaf(w0.x, c0.x, fmaf(w0.y, c0.y, a00));
                a01 = fmaf(w1.x, c0.z, fmaf(w1.y, c0.w, a01));
                a10 = fmaf(w0.x, c1.x, fmaf(w0.y, c1.y, a10));
                a11 = fmaf(w1.x, c1.z, fmaf(w1.y, c1.w, a11));
            }
            float bias = bq ? s.br[j] : s.bz[j];
            float p0 = a00 + a01 + bias;
            float p1 = a10 + a11 + bias;
            s.zr[bq][0][j] = __fdividef(1.f, 1.f + __expf(-p0));
            s.zr[bq][1][j] = __fdividef(1.f, 1.f + __expf(-p1));
        }
        __syncthreads();

        // stage 2.5: materialize combined_r (r applied once, not per dot term)
        {
            float v0, v1;
            if (j < DD) v0 = s.c[bq][j];
            else        v0 = s.zr[1][bq][j - DD] * s.c[bq][j];
            const int i2 = j + 128;
            if (i2 < DD + HH) v1 = s.zr[1][bq][i2 - DD] * s.c[bq][i2];
            else              v1 = s.c[bq][i2];
            s.cr[bq][j]  = v0;
            s.cr[bq][i2] = v1;
        }
        __syncthreads();

        // stage 3: h_tilde pre-activation, K split across thread halves
        {
            const int kbase = bq * 128;
            float a0 = 0.f, a1 = 0.f, b0a = 0.f, b1a = 0.f;
            #pragma unroll 8
            for (int kk = 0; kk < 128; kk += 2) {
                int k2 = (kbase + kk) >> 1;
                float2 w  = __half22float2(s.wh[k2][j]);
                float2 c0 = *(const float2*)&s.cr[0][kbase + kk];
                float2 c1 = *(const float2*)&s.cr[1][kbase + kk];
                a0  = fmaf(w.x, c0.x, a0);
                a1  = fmaf(w.y, c0.y, a1);
                b0a = fmaf(w.x, c1.x, b0a);
                b1a = fmaf(w.y, c1.y, b1a);
            }
            s.part[bq][0][j] = a0 + a1;
            s.part[bq][1][j] = b0a + b1a;
        }
        __syncthreads();

        // final: tanh, gate blend, state update, store
        {
            float pre = s.part[0][bq][j] + s.part[1][bq][j] + s.bh[j];
            float e   = __expf(2.f * pre);              // tanh = 1 - 2/(e^{2x}+1)
            float ht  = 1.f - __fdividef(2.f, e + 1.f); // saturates correctly at +-1
            float z   = s.zr[0][bq][j];
            float hp  = s.c[bq][DD + j];
            float hn  = fmaf(z, ht - hp, hp);           // (1-z)*hp + z*ht
            s.h[bq][j] = hn;
            out[((long)(b0 + bq) * TT + t) * HH + j] = hn;
        }
        __syncthreads();
    }
}

} // namespace

extern "C" void kernel_launch(void* const* d_in, const int* in_sizes, int n_in,
                              void* d_out, int out_size) {
    const float* inp = (const float*)d_in[0];
    const float* Wgx = (const float*)d_in[1];
    const float* bgx = (const float*)d_in[2];
    const float* Wgh = (const float*)d_in[3];
    const float* bgh = (const float*)d_in[4];
    const float* Wz  = (const float*)d_in[5];
    const float* bz  = (const float*)d_in[6];
    const float* Wr  = (const float*)d_in[7];
    const float* br  = (const float*)d_in[8];
    const float* Wh  = (const float*)d_in[9];
    const float* bh  = (const float*)d_in[10];
    float* out = (float*)d_out;

    static_assert(sizeof(Smem) < 232448, "smem layout exceeds opt-in limit");
    cudaFuncSetAttribute(grud_kernel,
                         cudaFuncAttributeMaxDynamicSharedMemorySize,
                         (int)sizeof(Smem));
    grud_kernel<<<BB / NB, NT, sizeof(Smem)>>>(
        inp, Wgx, bgx, Wgh, bgh, Wz, bz, Wr, br, Wh, bh, out);
}

// round 2
// speedup vs baseline: 1.0833x; 1.0833x over previous
#include <cuda_runtime.h>
#include <cuda_fp16.h>

namespace {

constexpr int BB = 256;   // batch
constexpr int TT = 512;   // time steps
constexpr int DD = 64;    // feature dim
constexpr int HH = 128;   // hidden dim
constexpr int NB = 2;     // batches per block
constexpr int NT = 256;   // threads per block
constexpr int KC = DD + HH + DD;   // 256 (combined width)

// fp16 weight packing, k-chunk-major so warp lanes (consecutive j) are
// conflict-free, and one LDS.128 of wzr feeds BOTH z and r gates.
struct __align__(16) Smem {
    uint4  wzr[KC / 4][HH];   // 131072 B : {Wz[j][4k..], Wr[j][4k..]} fp16
    uint2  whxm[32][HH];      //  32768 B : Wh over x/m region of combined
    uint2  whh[32][HH];       //  32768 B : Wh over h region of combined
    uint2  wgh[16][HH];       //  16384 B : W_gh
    float  c[NB][KC];         //   2048   combined = [x, h_pre, m]
    float  crh[NB][HH];       //   1024   r * h_pre
    float  in_s[4][NB][DD];   //   2048   x, x_last, m, d for this step
    float  h[NB][HH];         //   1024   recurrent state
    float  zg[NB][HH];        //   1024   z gate
    float  xm[NB][HH];        //   1024   Wh_x@x + Wh_m@m
    float  pA[2][NB][3][HH];  //   6144   K-split partials: z, r, xm
    float  pC[2][NB][HH];     //   2048   K-split partials: Wh_h@(r*h)
    float  bgx[DD], wgxd[DD];             //  512
    float  bgh[HH], bz_[HH], br_[HH], bh_[HH];  // 2048
};
// total = 231936 B <= 232448 B opt-in limit

__device__ __forceinline__ float2 mk2(float x, float y) { return make_float2(x, y); }

// Packed dual-FMA: d += a * b elementwise on fp32 pairs (single FFMA2 issue).
__device__ __forceinline__ void ffma2(float2& d, float2 a, float2 b) {
    asm("{\n\t"
        ".reg .b64 ra, rb, rd;\n\t"
        "mov.b64 ra, {%2, %3};\n\t"
        "mov.b64 rb, {%4, %5};\n\t"
        "mov.b64 rd, {%0, %1};\n\t"
        "fma.rn.f32x2 rd, ra, rb, rd;\n\t"
        "mov.b64 {%0, %1}, rd;\n\t"
        "}"
        : "+f"(d.x), "+f"(d.y)
        : "f"(a.x), "f"(a.y), "f"(b.x), "f"(b.y));
}

__device__ __forceinline__ unsigned pack_h2(float x, float y) {
    __half2 h = __floats2half2_rn(x, y);
    return *reinterpret_cast<unsigned*>(&h);
}
__device__ __forceinline__ float2 unpk(unsigned u) {
    return __half22float2(*reinterpret_cast<__half2*>(&u));
}

__global__ void __launch_bounds__(NT, 1) grud_kernel(
    const float* __restrict__ inp,   // [B,4,T,D]
    const float* __restrict__ Wgx, const float* __restrict__ bgx,
    const float* __restrict__ Wgh, const float* __restrict__ bgh,
    const float* __restrict__ Wz,  const float* __restrict__ bz,
    const float* __restrict__ Wr,  const float* __restrict__ br,
    const float* __restrict__ Wh,  const float* __restrict__ bh,
    float* __restrict__ out)         // [B,T,H]
{
    extern __shared__ char smem_raw[];
    Smem& s = *reinterpret_cast<Smem*>(smem_raw);
    const int tid = threadIdx.x;
    const int b0  = blockIdx.x * NB;

    // ---------------- preamble: weights -> smem fp16 (transposed) ----------
    for (int lin = tid; lin < HH * (KC / 4); lin += NT) {
        int j = lin >> 6, q4 = lin & 63;
        float4 a = *(const float4*)&Wz[j * KC + 4 * q4];
        float4 b = *(const float4*)&Wr[j * KC + 4 * q4];
        uint4 v;
        v.x = pack_h2(a.x, a.y);  v.y = pack_h2(a.z, a.w);
        v.z = pack_h2(b.x, b.y);  v.w = pack_h2(b.z, b.w);
        s.wzr[q4][j] = v;
    }
    for (int lin = tid; lin < HH * 32; lin += NT) {
        int j = lin >> 5, q = lin & 31;
        float4 g = *(const float4*)&Wh[j * KC + DD + 4 * q];        // h region
        s.whh[q][j] = make_uint2(pack_h2(g.x, g.y), pack_h2(g.z, g.w));
        int kc = (q < 16) ? 4 * q : 192 + 4 * (q - 16);             // x then m
        float4 x = *(const float4*)&Wh[j * KC + kc];
        s.whxm[q][j] = make_uint2(pack_h2(x.x, x.y), pack_h2(x.z, x.w));
    }
    for (int lin = tid; lin < HH * 16; lin += NT) {
        int j = lin >> 4, q = lin & 15;
        float4 a = *(const float4*)&Wgh[j * DD + 4 * q];
        s.wgh[q][j] = make_uint2(pack_h2(a.x, a.y), pack_h2(a.z, a.w));
    }
    if (tid < HH) {
        s.bgh[tid] = bgh[tid]; s.bz_[tid] = bz[tid];
        s.br_[tid] = br[tid];  s.bh_[tid] = bh[tid];
        s.h[0][tid] = 0.f;     s.h[1][tid] = 0.f;
    }
    if (tid < DD) {
        s.bgx[tid]  = bgx[tid];
        s.wgxd[tid] = Wgx[tid * DD + tid];   // (eye * W_gx) diagonal
    }

    // ---------------- input prefetch (one (ch,d) per thread, both batches) -
    const int ch = (tid >> 6) & 3;
    const int dl = tid & 63;
    const long base0 = ((long)(b0 * 4 + ch) * TT) * DD + dl;
    const long base1 = base0 + 4L * TT * DD;
    float nx0 = inp[base0];
    float nx1 = inp[base1];

    const int sel = tid >> 7;   // batch selector (elementwise) / K-half (GEMV)
    const int j   = tid & 127;  // output row

    for (int t = 0; t < TT; ++t) {
        // publish this step's inputs, prefetch next step's
        s.in_s[ch][0][dl] = nx0;
        s.in_s[ch][1][dl] = nx1;
        const int tn = (t + 1 < TT) ? (t + 1) : t;
        nx0 = inp[base0 + (long)tn * DD];
        nx1 = inp[base1 + (long)tn * DD];
        __syncthreads();                                   // sync 1

        // ---- stage 0: delta_h matvec (full K per thread, own batch) +
        //               h_pre, x-update, m slot ----
        {
            float2 ag = mk2(0.f, 0.f);
            #pragma unroll
            for (int q = 0; q < 16; ++q) {
                uint2 w = s.wgh[q][j];
                float4 d4 = *(const float4*)&s.in_s[3][sel][4 * q];
                ffma2(ag, unpk(w.x), mk2(d4.x, d4.y));
                ffma2(ag, unpk(w.y), mk2(d4.z, d4.w));
            }
            float pre = ag.x + ag.y + s.bgh[j];
            float dh  = __expf(-fmaxf(pre, 0.f));
            s.c[sel][DD + j] = dh * s.h[sel][j];
        }
        if (tid < 128) {
            int b2 = tid >> 6, d = tid & 63;
            float dd = s.in_s[3][b2][d];
            float dx = __expf(-fmaxf(fmaf(dd, s.wgxd[d], s.bgx[d]), 0.f));
            float m  = s.in_s[2][b2][d];
            float xv = m * s.in_s[0][b2][d] + (1.f - m) * (dx * s.in_s[1][b2][d]);
            s.c[b2][d] = xv;
            s.c[b2][DD + HH + d] = m;
        }
        __syncthreads();                                   // sync 2

        // ---- stage A: z, r, and Wh_xm partials; K split across sel ----
        {
            float2 az0 = mk2(0.f,0.f), az1 = mk2(0.f,0.f);
            float2 ar0 = mk2(0.f,0.f), ar1 = mk2(0.f,0.f);
            float2 ax0 = mk2(0.f,0.f), ax1 = mk2(0.f,0.f);
            int q4 = sel * 32;
            for (int half_ = 0; half_ < 2; ++half_) {
                const bool doxm = (half_ == sel);   // warp-uniform
                #pragma unroll 4
                for (int i = 0; i < 16; ++i, ++q4) {
                    uint4 w = s.wzr[q4][j];
                    float4 c0 = *(const float4*)&s.c[0][4 * q4];
                    float4 c1 = *(const float4*)&s.c[1][4 * q4];
                    float2 lo0 = mk2(c0.x, c0.y), hi0 = mk2(c0.z, c0.w);
                    float2 lo1 = mk2(c1.x, c1.y), hi1 = mk2(c1.z, c1.w);
                    float2 wz0 = unpk(w.x), wz1 = unpk(w.y);
                    float2 wr0 = unpk(w.z), wr1 = unpk(w.w);
                    ffma2(az0, wz0, lo0); ffma2(az0, wz1, hi0);
                    ffma2(az1, wz0, lo1); ffma2(az1, wz1, hi1);
                    ffma2(ar0, wr0, lo0); ffma2(ar0, wr1, hi0);
                    ffma2(ar1, wr0, lo1); ffma2(ar1, wr1, hi1);
                    if (doxm) {
                        // whxm index: sel=0 -> q4 in [0,16) -> q=q4
                        //             sel=1 -> q4 in [48,64) -> q=q4-32
                        uint2 wx = s.whxm[q4 - sel * 32][j];
                        float2 w0 = unpk(wx.x), w1 = unpk(wx.y);
                        ffma2(ax0, w0, lo0); ffma2(ax0, w1, hi0);
                        ffma2(ax1, w0, lo1); ffma2(ax1, w1, hi1);
                    }
                }
            }
            s.pA[sel][0][0][j] = az0.x + az0.y;
            s.pA[sel][1][0][j] = az1.x + az1.y;
            s.pA[sel][0][1][j] = ar0.x + ar0.y;
            s.pA[sel][1][1][j] = ar1.x + ar1.y;
            s.pA[sel][0][2][j] = ax0.x + ax0.y;
            s.pA[sel][1][2][j] = ax1.x + ax1.y;
        }
        __syncthreads();                                   // sync 3

        // ---- stage A-reduce: gates + r*h_pre + xm sum ----
        {
            float zp = s.pA[0][sel][0][j] + s.pA[1][sel][0][j] + s.bz_[j];
            float rp = s.pA[0][sel][1][j] + s.pA[1][sel][1][j] + s.br_[j];
            float z  = __fdividef(1.f, 1.f + __expf(-zp));
            float r  = __fdividef(1.f, 1.f + __expf(-rp));
            s.zg[sel][j]  = z;
            s.xm[sel][j]  = s.pA[0][sel][2][j] + s.pA[1][sel][2][j];
            s.crh[sel][j] = r * s.c[sel][DD + j];
        }
        __syncthreads();                                   // sync 4

        // ---- stage C: Wh_h @ (r*h_pre), K=128 split across sel ----
        {
            float2 a0 = mk2(0.f,0.f), a1 = mk2(0.f,0.f);
            #pragma unroll 4
            for (int i = 0; i < 16; ++i) {
                int q = sel * 16 + i;
                uint2 w = s.whh[q][j];
                float4 r0 = *(const float4*)&s.crh[0][4 * q];
                float4 r1 = *(const float4*)&s.crh[1][4 * q];
                float2 w0 = unpk(w.x), w1 = unpk(w.y);
                ffma2(a0, w0, mk2(r0.x, r0.y)); ffma2(a0, w1, mk2(r0.z, r0.w));
                ffma2(a1, w0, mk2(r1.x, r1.y)); ffma2(a1, w1, mk2(r1.z, r1.w));
            }
            s.pC[sel][0][j] = a0.x + a0.y;
            s.pC[sel][1][j] = a1.x + a1.y;
        }
        __syncthreads();                                   // sync 5

        // ---- final: tanh, blend, state update, store ----
        {
            float pre = s.pC[0][sel][j] + s.pC[1][sel][j]
                      + s.xm[sel][j] + s.bh_[j];
            float e   = __expf(2.f * pre);
            float ht  = 1.f - __fdividef(2.f, e + 1.f);    // tanh
            float z   = s.zg[sel][j];
            float hp  = s.c[sel][DD + j];
            float hn  = fmaf(z, ht - hp, hp);
            s.h[sel][j] = hn;
            out[((long)(b0 + sel) * TT + t) * HH + j] = hn;
        }
        // no sync needed here: next publish touches only in_s, and sync 1/2
        // order this stage's reads/writes against next step's producers.
    }
}

} // namespace

extern "C" void kernel_launch(void* const* d_in, const int* in_sizes, int n_in,
                              void* d_out, int out_size) {
    const float* inp = (const float*)d_in[0];
    const float* Wgx = (const float*)d_in[1];
    const float* bgx = (const float*)d_in[2];
    const float* Wgh = (const float*)d_in[3];
    const float* bgh = (const float*)d_in[4];
    const float* Wz  = (const float*)d_in[5];
    const float* bz  = (const float*)d_in[6];
    const float* Wr  = (const float*)d_in[7];
    const float* br  = (const float*)d_in[8];
    const float* Wh  = (const float*)d_in[9];
    const float* bh  = (const float*)d_in[10];
    float* out = (float*)d_out;

    static_assert(sizeof(Smem) <= 232448, "smem layout exceeds opt-in limit");
    cudaFuncSetAttribute(grud_kernel,
                         cudaFuncAttributeMaxDynamicSharedMemorySize,
                         (int)sizeof(Smem));
    grud_kernel<<<BB / NB, NT, sizeof(Smem)>>>(
        inp, Wgx, bgx, Wgh, bgh, Wz, bz, Wr, br, Wh, bh, out);
}

// round 3
// speedup vs baseline: 1.1962x; 1.1043x over previous
#include <cuda_runtime.h>
#include <cuda_fp16.h>

namespace {

constexpr int BB = 256;   // batch
constexpr int TT = 512;   // time steps
constexpr int DD = 64;    // feature dim
constexpr int HH = 128;   // hidden dim
constexpr int NB = 2;     // batches per block
constexpr int NT = 512;   // threads per block (16 warps)
constexpr int KC = DD + HH + DD;   // 256 combined width

// Weights fp16, k-chunk-major: warp lanes = consecutive j -> conflict-free.
// One LDS.128 of wzr feeds BOTH gates and BOTH batches (weights read once).
struct __align__(16) Smem {
    uint4  wzr[KC / 4][HH];   // 131072 : {Wz 4k, Wr 4k} fp16 per (q4,j)
    uint2  whxm[32][HH];      //  32768 : Wh rows 0-15 = x part, 16-31 = m part
    uint2  whh[32][HH];       //  32768 : Wh over h region
    uint2  wgh[16][HH];       //  16384 : W_gh
    float  c[NB][192];        //   1536 : combined = [x(64), h_pre(128)] (m from in_s)
    float  crh[NB][HH];       //   1024 : r * h_pre
    float  in_s[4][NB][DD];   //   2048 : x, x_last, m, d for this step
    float  h[NB][HH];         //   1024 : recurrent state
    float  zg[NB][HH];        //   1024 : z gate
    union {                   //   8192 : stage-A z/r partials, then stage-C partials
        float pZR[4][NB][2][HH];
        float pC_[4][NB][HH];
    };
    float  pAx[2][NB][HH];    //   2048 : xm partials; [0] holds xm sum after reduce
    float  bgx[DD], wgxd[DD]; //    512
    float  bgh_[HH], bh_[HH]; //   1024
    __half2 bzr[HH];          //    512 : {bz, br}
};
// total = 231936 B <= 232448 opt-in limit

__device__ __forceinline__ float2 mk2(float x, float y) { return make_float2(x, y); }

// Packed dual-FMA (single FFMA2 issue on sm_103a).
__device__ __forceinline__ void ffma2(float2& d, float2 a, float2 b) {
    asm("{\n\t"
        ".reg .b64 ra, rb, rd;\n\t"
        "mov.b64 ra, {%2, %3};\n\t"
        "mov.b64 rb, {%4, %5};\n\t"
        "mov.b64 rd, {%0, %1};\n\t"
        "fma.rn.f32x2 rd, ra, rb, rd;\n\t"
        "mov.b64 {%0, %1}, rd;\n\t"
        "}"
        : "+f"(d.x), "+f"(d.y)
        : "f"(a.x), "f"(a.y), "f"(b.x), "f"(b.y));
}

__device__ __forceinline__ unsigned pack_h2(float x, float y) {
    __half2 h = __floats2half2_rn(x, y);
    return *reinterpret_cast<unsigned*>(&h);
}
__device__ __forceinline__ float2 unpk(unsigned u) {
    return __half22float2(*reinterpret_cast<__half2*>(&u));
}

__global__ void __launch_bounds__(NT, 1) grud_kernel(
    const float* __restrict__ inp,   // [B,4,T,D]
    const float* __restrict__ Wgx, const float* __restrict__ bgx,
    const float* __restrict__ Wgh, const float* __restrict__ bgh,
    const float* __restrict__ Wz,  const float* __restrict__ bz,
    const float* __restrict__ Wr,  const float* __restrict__ br,
    const float* __restrict__ Wh,  const float* __restrict__ bh,
    float* __restrict__ out)         // [B,T,H]
{
    extern __shared__ char smem_raw[];
    Smem& s = *reinterpret_cast<Smem*>(smem_raw);
    const int tid = threadIdx.x;
    const int b0  = blockIdx.x * NB;

    // ---------------- preamble: weights -> smem fp16 (transposed) ----------
    for (int lin = tid; lin < HH * (KC / 4); lin += NT) {
        int j = lin >> 6, q4 = lin & 63;
        float4 a = *(const float4*)&Wz[j * KC + 4 * q4];
        float4 b = *(const float4*)&Wr[j * KC + 4 * q4];
        uint4 v;
        v.x = pack_h2(a.x, a.y);  v.y = pack_h2(a.z, a.w);
        v.z = pack_h2(b.x, b.y);  v.w = pack_h2(b.z, b.w);
        s.wzr[q4][j] = v;
    }
    for (int lin = tid; lin < HH * 32; lin += NT) {
        int j = lin >> 5, q = lin & 31;
        float4 g = *(const float4*)&Wh[j * KC + DD + 4 * q];        // h region
        s.whh[q][j] = make_uint2(pack_h2(g.x, g.y), pack_h2(g.z, g.w));
        int kc = (q < 16) ? 4 * q : 192 + 4 * (q - 16);             // x then m
        float4 x = *(const float4*)&Wh[j * KC + kc];
        s.whxm[q][j] = make_uint2(pack_h2(x.x, x.y), pack_h2(x.z, x.w));
    }
    for (int lin = tid; lin < HH * 16; lin += NT) {
        int j = lin >> 4, q = lin & 15;
        float4 a = *(const float4*)&Wgh[j * DD + 4 * q];
        s.wgh[q][j] = make_uint2(pack_h2(a.x, a.y), pack_h2(a.z, a.w));
    }
    if (tid < HH) {
        s.bgh_[tid] = bgh[tid];
        s.bh_[tid]  = bh[tid];
        s.bzr[tid]  = __floats2half2_rn(bz[tid], br[tid]);
        s.h[0][tid] = 0.f;  s.h[1][tid] = 0.f;
    }
    if (tid < DD) {
        s.bgx[tid]  = bgx[tid];
        s.wgxd[tid] = Wgx[tid * DD + tid];   // (eye * W_gx) diagonal
    }

    // -------- input prefetch: one (ch, bq, d) element per thread ----------
    const int ch = tid >> 7;          // 0..3
    const int bi = (tid >> 6) & 1;    // batch for input ownership
    const int dl = tid & 63;
    const long ibase = ((long)((b0 + bi) * 4 + ch) * TT) * DD + dl;
    float nx = inp[ibase];

    const int q = tid >> 7;    // K-quarter for GEMV stages
    const int j = tid & 127;   // output row

    for (int t = 0; t < TT; ++t) {
        // publish this step's input element, prefetch next
        s.in_s[ch][bi][dl] = nx;
        const int tn = (t + 1 < TT) ? (t + 1) : t;
        nx = inp[ibase + (long)tn * DD];
        __syncthreads();                                   // sync 1

        // ---- stage 0: delta_h (tids 256..511, full K=64 per thread) +
        //               x-update (tids 0..127) ----
        if (tid >= 256) {
            int bq = (tid >> 7) & 1;
            float2 ag = mk2(0.f, 0.f);
            #pragma unroll
            for (int i = 0; i < 16; ++i) {
                uint2 w = s.wgh[i][j];
                float4 d4 = *(const float4*)&s.in_s[3][bq][4 * i];
                ffma2(ag, unpk(w.x), mk2(d4.x, d4.y));
                ffma2(ag, unpk(w.y), mk2(d4.z, d4.w));
            }
            float pre = ag.x + ag.y + s.bgh_[j];
            float dh  = __expf(-fmaxf(pre, 0.f));
            s.c[bq][DD + j] = dh * s.h[bq][j];
        } else if (tid < 128) {
            int b2 = tid >> 6, d = tid & 63;
            float dd = s.in_s[3][b2][d];
            float dx = __expf(-fmaxf(fmaf(dd, s.wgxd[d], s.bgx[d]), 0.f));
            float m  = s.in_s[2][b2][d];
            s.c[b2][d] = m * s.in_s[0][b2][d] + (1.f - m) * (dx * s.in_s[1][b2][d]);
        }
        __syncthreads();                                   // sync 2

        // ---- stage A: z, r (+ xm on quarters 0,3); K split 4 ways ----
        {
            // quarter q covers combined k in [64q, 64q+64):
            //   q=0 -> x (c[0..63]); q=1,2 -> h (c[64..191]); q=3 -> m (in_s[2])
            const float* cp0 = (q < 3) ? &s.c[0][64 * q] : &s.in_s[2][0][0];
            const float* cp1 = (q < 3) ? &s.c[1][64 * q] : &s.in_s[2][1][0];
            float2 az0 = mk2(0.f,0.f), az1 = mk2(0.f,0.f);
            float2 ar0 = mk2(0.f,0.f), ar1 = mk2(0.f,0.f);
            float2 ax0 = mk2(0.f,0.f), ax1 = mk2(0.f,0.f);
            const bool doxm = (q == 0) || (q == 3);        // warp-uniform
            const int xrow = (q == 0) ? 0 : 16;
            #pragma unroll
            for (int i = 0; i < 16; ++i) {
                uint4 w = s.wzr[16 * q + i][j];
                float4 c0 = *(const float4*)(cp0 + 4 * i);
                float4 c1 = *(const float4*)(cp1 + 4 * i);
                float2 lo0 = mk2(c0.x, c0.y), hi0 = mk2(c0.z, c0.w);
                float2 lo1 = mk2(c1.x, c1.y), hi1 = mk2(c1.z, c1.w);
                float2 wz0 = unpk(w.x), wz1 = unpk(w.y);
                float2 wr0 = unpk(w.z), wr1 = unpk(w.w);
                ffma2(az0, wz0, lo0); ffma2(az0, wz1, hi0);
                ffma2(az1, wz0, lo1); ffma2(az1, wz1, hi1);
                ffma2(ar0, wr0, lo0); ffma2(ar0, wr1, hi0);
                ffma2(ar1, wr0, lo1); ffma2(ar1, wr1, hi1);
                if (doxm) {
                    uint2 wx = s.whxm[xrow + i][j];
                    float2 w0 = unpk(wx.x), w1 = unpk(wx.y);
                    ffma2(ax0, w0, lo0); ffma2(ax0, w1, hi0);
                    ffma2(ax1, w0, lo1); ffma2(ax1, w1, hi1);
                }
            }
            s.pZR[q][0][0][j] = az0.x + az0.y;
            s.pZR[q][1][0][j] = az1.x + az1.y;
            s.pZR[q][0][1][j] = ar0.x + ar0.y;
            s.pZR[q][1][1][j] = ar1.x + ar1.y;
            if (doxm) {
                int xi = (q == 0) ? 0 : 1;
                s.pAx[xi][0][j] = ax0.x + ax0.y;
                s.pAx[xi][1][j] = ax1.x + ax1.y;
            }
        }
        __syncthreads();                                   // sync 3

        // ---- A-reduce: gates, r*h_pre, xm sum (one output per thread) ----
        {
            int g  = tid >> 8;          // 0 = z (+xm), 1 = r (+crh)
            int bq = (tid >> 7) & 1;
            float p = s.pZR[0][bq][g][j] + s.pZR[1][bq][g][j]
                    + s.pZR[2][bq][g][j] + s.pZR[3][bq][g][j];
            float2 bz2 = unpk(*reinterpret_cast<const unsigned*>(&s.bzr[j]));
            if (g == 0) {
                float z = __fdividef(1.f, 1.f + __expf(-(p + bz2.x)));
                s.zg[bq][j] = z;
                s.pAx[0][bq][j] = s.pAx[0][bq][j] + s.pAx[1][bq][j];  // xm
            } else {
                float r = __fdividef(1.f, 1.f + __expf(-(p + bz2.y)));
                s.crh[bq][j] = r * s.c[bq][DD + j];
            }
        }
        __syncthreads();                                   // sync 4

        // ---- stage C: Wh_h @ (r*h_pre), K=128 split 4 ways ----
        {
            float2 a0 = mk2(0.f,0.f), a1 = mk2(0.f,0.f);
            #pragma unroll
            for (int i = 0; i < 8; ++i) {
                int row = 8 * q + i;
                uint2 w = s.whh[row][j];
                float4 r0 = *(const float4*)&s.crh[0][4 * row];
                float4 r1 = *(const float4*)&s.crh[1][4 * row];
                float2 w0 = unpk(w.x), w1 = unpk(w.y);
                ffma2(a0, w0, mk2(r0.x, r0.y)); ffma2(a0, w1, mk2(r0.z, r0.w));
                ffma2(a1, w0, mk2(r1.x, r1.y)); ffma2(a1, w1, mk2(r1.z, r1.w));
            }
            s.pC_[q][0][j] = a0.x + a0.y;
            s.pC_[q][1][j] = a1.x + a1.y;
        }
        __syncthreads();                                   // sync 5

        // ---- final: tanh, blend, state update, store (tids 0..255) ----
        if (tid < 256) {
            int bq = tid >> 7;
            float pre = s.pC_[0][bq][j] + s.pC_[1][bq][j]
                      + s.pC_[2][bq][j] + s.pC_[3][bq][j]
                      + s.pAx[0][bq][j] + s.bh_[j];
            float e   = __expf(2.f * pre);
            float ht  = 1.f - __fdividef(2.f, e + 1.f);    // tanh
            float z   = s.zg[bq][j];
            float hp  = s.c[bq][DD + j];
            float hn  = fmaf(z, ht - hp, hp);
            s.h[bq][j] = hn;
            out[((long)(b0 + bq) * TT + t) * HH + j] = hn;
        }
        // no trailing sync: sync1 of the next step orders final's writes
        // (h, out) against their next readers; in_s publishing races nothing
        // (all step-t readers of in_s finished before sync 3).
    }
}

} // namespace

extern "C" void kernel_launch(void* const* d_in, const int* in_sizes, int n_in,
                              void* d_out, int out_size) {
    const float* inp = (const float*)d_in[0];
    const float* Wgx = (const float*)d_in[1];
    const float* bgx = (const float*)d_in[2];
    const float* Wgh = (const float*)d_in[3];
    const float* bgh = (const float*)d_in[4];
    const float* Wz  = (const float*)d_in[5];
    const float* bz  = (const float*)d_in[6];
    const float* Wr  = (const float*)d_in[7];
    const float* br  = (const float*)d_in[8];
    const float* Wh  = (const float*)d_in[9];
    const float* bh  = (const float*)d_in[10];
    float* out = (float*)d_out;

    static_assert(sizeof(Smem) <= 232448, "smem layout exceeds opt-in limit");
    cudaFuncSetAttribute(grud_kernel,
                         cudaFuncAttributeMaxDynamicSharedMemorySize,
                         (int)sizeof(Smem));
    grud_kernel<<<BB / NB, NT, sizeof(Smem)>>>(
        inp, Wgx, bgx, Wgh, bgh, Wz, bz, Wr, br, Wh, bh, out);
}